// round 1
// baseline (speedup 1.0000x reference)
#include <cuda_runtime.h>
#include <cuda_bf16.h>
#include <cstdint>

// Problem constants (fixed by the reference setup_inputs).
constexpr int B  = 4096;   // batch rows
constexpr int D  = 784;    // feature dim
constexpr int O1 = 8192;   // pair terms
constexpr int O2 = 8192;   // triple terms
constexpr int OT = O1 + O2; // 16384 outputs per row
constexpr int R  = 4;      // rows per block
constexpr int NTHREADS = 256;

__global__ __launch_bounds__(NTHREADS)
void random_de_kernel(const float* __restrict__ x,
                      const int*   __restrict__ idx1,
                      const int*   __restrict__ idx2,
                      float*       __restrict__ out)
{
    __shared__ float xs[R][D];

    const int row0 = blockIdx.x * R;

    // Stage R contiguous rows of x into shared memory (R*D floats, float4 loads).
    {
        const float4* src = reinterpret_cast<const float4*>(x + (size_t)row0 * D);
        float4* dst = reinterpret_cast<float4*>(&xs[0][0]);
        #pragma unroll 2
        for (int i = threadIdx.x; i < R * D / 4; i += NTHREADS) {
            dst[i] = src[i];
        }
    }
    __syncthreads();

    const int tid = threadIdx.x;

    // ---- Part 1: pair products (outputs [0, O1)) ----
    // Each iteration: 4 consecutive outputs -> 8 indices = two int4 loads (32B aligned).
    {
        const int4* idx1v = reinterpret_cast<const int4*>(idx1);
        #pragma unroll 2
        for (int g = tid; g < O1 / 4; g += NTHREADS) {
            const int o = g * 4;
            const int4 a = __ldg(&idx1v[g * 2 + 0]);
            const int4 b = __ldg(&idx1v[g * 2 + 1]);
            #pragma unroll
            for (int r = 0; r < R; r++) {
                float4 v;
                v.x = xs[r][a.x] * xs[r][a.y];
                v.y = xs[r][a.z] * xs[r][a.w];
                v.z = xs[r][b.x] * xs[r][b.y];
                v.w = xs[r][b.z] * xs[r][b.w];
                *reinterpret_cast<float4*>(out + (size_t)(row0 + r) * OT + o) = v;
            }
        }
    }

    // ---- Part 2: triple products (outputs [O1, O1+O2)) ----
    // Each iteration: 4 consecutive outputs -> 12 indices = three int4 loads (48B aligned).
    {
        const int4* idx2v = reinterpret_cast<const int4*>(idx2);
        #pragma unroll 2
        for (int g = tid; g < O2 / 4; g += NTHREADS) {
            const int o = g * 4;
            const int4 c0 = __ldg(&idx2v[g * 3 + 0]);
            const int4 c1 = __ldg(&idx2v[g * 3 + 1]);
            const int4 c2 = __ldg(&idx2v[g * 3 + 2]);
            #pragma unroll
            for (int r = 0; r < R; r++) {
                float4 v;
                v.x = xs[r][c0.x] * xs[r][c0.y] * xs[r][c0.z];
                v.y = xs[r][c0.w] * xs[r][c1.x] * xs[r][c1.y];
                v.z = xs[r][c1.z] * xs[r][c1.w] * xs[r][c2.x];
                v.w = xs[r][c2.y] * xs[r][c2.z] * xs[r][c2.w];
                *reinterpret_cast<float4*>(out + (size_t)(row0 + r) * OT + O1 + o) = v;
            }
        }
    }
}

extern "C" void kernel_launch(void* const* d_in, const int* in_sizes, int n_in,
                              void* d_out, int out_size)
{
    const float* x    = (const float*)d_in[0];
    const int*   idx1 = (const int*)d_in[1];
    const int*   idx2 = (const int*)d_in[2];
    float*       out  = (float*)d_out;

    dim3 grid(B / R);
    random_de_kernel<<<grid, NTHREADS>>>(x, idx1, idx2, out);
}

// round 2
// speedup vs baseline: 1.1304x; 1.1304x over previous
#include <cuda_runtime.h>
#include <cuda_bf16.h>
#include <cstdint>

// Problem constants (fixed by the reference setup_inputs).
constexpr int B  = 4096;   // batch rows
constexpr int D  = 784;    // feature dim
constexpr int O1 = 8192;   // pair terms
constexpr int O2 = 8192;   // triple terms
constexpr int OT = O1 + O2; // 16384 outputs per row
constexpr int R  = 4;      // rows per block (packed in float4 lanes)
constexpr int NTHREADS = 256;

__device__ __forceinline__ float4 mul4(float4 a, float4 b) {
    return make_float4(a.x * b.x, a.y * b.y, a.z * b.z, a.w * b.w);
}

__global__ __launch_bounds__(NTHREADS)
void random_de_kernel(const float* __restrict__ x,
                      const int*   __restrict__ idx1,
                      const int*   __restrict__ idx2,
                      float*       __restrict__ out)
{
    // Transposed layout: xs[d] = {row0[d], row1[d], row2[d], row3[d]}.
    // One LDS.128 fetches a gathered feature for all 4 rows.
    __shared__ float4 xs[D];

    const int row0 = blockIdx.x * R;
    const int tid  = threadIdx.x;

    // Stage: read rows with coalesced float4 global loads, scatter into
    // the transposed smem layout (tiny vs the main gather traffic).
    {
        float* xsf = reinterpret_cast<float*>(xs);
        #pragma unroll 2
        for (int i = tid; i < (R * D) / 4; i += NTHREADS) {
            const int r  = i / (D / 4);
            const int dd = (i % (D / 4)) * 4;
            const float4 v = *reinterpret_cast<const float4*>(
                x + (size_t)(row0 + r) * D + dd);
            xsf[(dd + 0) * R + r] = v.x;
            xsf[(dd + 1) * R + r] = v.y;
            xsf[(dd + 2) * R + r] = v.z;
            xsf[(dd + 3) * R + r] = v.w;
        }
    }
    __syncthreads();

    float* outp = out + (size_t)row0 * OT;

    // ---- Part 1: pair products (outputs [0, O1)) ----
    {
        const int4* idx1v = reinterpret_cast<const int4*>(idx1);
        #pragma unroll 2
        for (int g = tid; g < O1 / 4; g += NTHREADS) {
            const int o = g * 4;
            const int4 a = __ldg(&idx1v[g * 2 + 0]);
            const int4 b = __ldg(&idx1v[g * 2 + 1]);
            // vj = product for output (o+j), all 4 rows in lanes
            const float4 v0 = mul4(xs[a.x], xs[a.y]);
            const float4 v1 = mul4(xs[a.z], xs[a.w]);
            const float4 v2 = mul4(xs[b.x], xs[b.y]);
            const float4 v3 = mul4(xs[b.z], xs[b.w]);
            // register transpose -> coalesced float4 store per row
            *reinterpret_cast<float4*>(outp + 0 * (size_t)OT + o) = make_float4(v0.x, v1.x, v2.x, v3.x);
            *reinterpret_cast<float4*>(outp + 1 * (size_t)OT + o) = make_float4(v0.y, v1.y, v2.y, v3.y);
            *reinterpret_cast<float4*>(outp + 2 * (size_t)OT + o) = make_float4(v0.z, v1.z, v2.z, v3.z);
            *reinterpret_cast<float4*>(outp + 3 * (size_t)OT + o) = make_float4(v0.w, v1.w, v2.w, v3.w);
        }
    }

    // ---- Part 2: triple products (outputs [O1, O1+O2)) ----
    {
        const int4* idx2v = reinterpret_cast<const int4*>(idx2);
        #pragma unroll 2
        for (int g = tid; g < O2 / 4; g += NTHREADS) {
            const int o = g * 4;
            const int4 c0 = __ldg(&idx2v[g * 3 + 0]);
            const int4 c1 = __ldg(&idx2v[g * 3 + 1]);
            const int4 c2 = __ldg(&idx2v[g * 3 + 2]);
            const float4 v0 = mul4(mul4(xs[c0.x], xs[c0.y]), xs[c0.z]);
            const float4 v1 = mul4(mul4(xs[c0.w], xs[c1.x]), xs[c1.y]);
            const float4 v2 = mul4(mul4(xs[c1.z], xs[c1.w]), xs[c2.x]);
            const float4 v3 = mul4(mul4(xs[c2.y], xs[c2.z]), xs[c2.w]);
            *reinterpret_cast<float4*>(outp + 0 * (size_t)OT + O1 + o) = make_float4(v0.x, v1.x, v2.x, v3.x);
            *reinterpret_cast<float4*>(outp + 1 * (size_t)OT + O1 + o) = make_float4(v0.y, v1.y, v2.y, v3.y);
            *reinterpret_cast<float4*>(outp + 2 * (size_t)OT + O1 + o) = make_float4(v0.z, v1.z, v2.z, v3.z);
            *reinterpret_cast<float4*>(outp + 3 * (size_t)OT + O1 + o) = make_float4(v0.w, v1.w, v2.w, v3.w);
        }
    }
}

extern "C" void kernel_launch(void* const* d_in, const int* in_sizes, int n_in,
                              void* d_out, int out_size)
{
    const float* x    = (const float*)d_in[0];
    const int*   idx1 = (const int*)d_in[1];
    const int*   idx2 = (const int*)d_in[2];
    float*       out  = (float*)d_out;

    dim3 grid(B / R);
    random_de_kernel<<<grid, NTHREADS>>>(x, idx1, idx2, out);
}